// round 12
// baseline (speedup 1.0000x reference)
#include <cuda_runtime.h>
#include <cuda_bf16.h>
#include <mma.h>
#include <cstdint>
#include <math.h>

using namespace nvcuda;

#define NR 8192
#define DD 512
#define BATCH 2048
#define NCLS 200

// ---------------- scratch (__device__ globals, no allocation) ----------------
__device__ signed char g_q[(size_t)NR * DD];     // quantized normalized features (4 MB)
__device__ float g_rows[(size_t)NR * 8];         // per-row {T,P,Q,R,Pv,Qv,Rv,pad} (256 KB)
__device__ int g_chist[NCLS];
__device__ double g_ce;
__device__ double g_np;
__device__ unsigned g_done;
__device__ unsigned char g_tcls[BATCH];

// ---------------- reductions ----------------
template <int BS>
__device__ __forceinline__ float blockReduceSum(float v, float* sbuf) {
#pragma unroll
    for (int o = 16; o > 0; o >>= 1) v += __shfl_xor_sync(0xffffffffu, v, o);
    int w = threadIdx.x >> 5;
    if ((threadIdx.x & 31) == 0) sbuf[w] = v;
    __syncthreads();
    if (w == 0) {
        v = (threadIdx.x < BS / 32) ? sbuf[threadIdx.x] : 0.0f;
#pragma unroll
        for (int o = 16; o > 0; o >>= 1) v += __shfl_xor_sync(0xffffffffu, v, o);
        if (threadIdx.x == 0) sbuf[0] = v;
    }
    __syncthreads();
    float r = sbuf[0];
    __syncthreads();
    return r;
}
template <int BS>
__device__ __forceinline__ float blockReduceMax(float v, float* sbuf) {
#pragma unroll
    for (int o = 16; o > 0; o >>= 1) v = fmaxf(v, __shfl_xor_sync(0xffffffffu, v, o));
    int w = threadIdx.x >> 5;
    if ((threadIdx.x & 31) == 0) sbuf[w] = v;
    __syncthreads();
    if (w == 0) {
        v = (threadIdx.x < BS / 32) ? sbuf[threadIdx.x] : -3.0e38f;
#pragma unroll
        for (int o = 16; o > 0; o >>= 1) v = fmaxf(v, __shfl_xor_sync(0xffffffffu, v, o));
        if (threadIdx.x == 0) sbuf[0] = v;
    }
    __syncthreads();
    float r = sbuf[0];
    __syncthreads();
    return r;
}

// ---------------- decode targets + class histogram ----------------
__global__ void decode_targets_kernel(const unsigned int* __restrict__ traw) {
    __shared__ int hist[NCLS];
    if (threadIdx.x == 0) { g_ce = 0.0; g_np = 0.0; g_done = 0u; }
    for (int c = threadIdx.x; c < NCLS; c += blockDim.x) hist[c] = 0;
    __syncthreads();
    int nz = 0;
    for (int i = threadIdx.x; i < BATCH / 2; i += blockDim.x)
        if (traw[2 * i + 1] != 0u) nz = 1;
    if (__syncthreads_or(nz)) {           // int32 layout
        for (int i = threadIdx.x; i < BATCH; i += blockDim.x) {
            unsigned char c = (unsigned char)traw[i];
            g_tcls[i] = c;
            atomicAdd(&hist[c], 1);
        }
    } else {                              // little-endian int64 layout
        for (int i = threadIdx.x; i < BATCH; i += blockDim.x) {
            unsigned char c = (unsigned char)traw[2 * i];
            g_tcls[i] = c;
            atomicAdd(&hist[c], 1);
        }
    }
    __syncthreads();
    for (int c = threadIdx.x; c < NCLS; c += blockDim.x) g_chist[c] = hist[c];
}

// ---------------- fused normalize(+quantize) + CE + g_rows zeroing ----------------
#define ZBLK 64
__global__ void norm_ce_kernel(const float* __restrict__ x, const float* __restrict__ pred) {
    __shared__ float sbuf[8];
    const int b = blockIdx.x;
    if (b < NR) {
        const float* xr = x + (size_t)b * DD;
        float s = 0.0f;
        for (int c = threadIdx.x; c < DD; c += 128) { float v = xr[c]; s += v * v; }
        s = blockReduceSum<128>(s, sbuf);
        float inv = 127.0f / fmaxf(sqrtf(s), 1e-12f);
        for (int c = threadIdx.x; c < DD; c += 128)
            g_q[(size_t)b * DD + c] = (signed char)__float2int_rn(xr[c] * inv);
    } else if (b < NR + BATCH) {
        const int i = b - NR;
        const float* p = pred + (size_t)i * NCLS;
        float m = -3.0e38f, slin = 0.0f;
        for (int c = threadIdx.x; c < NCLS; c += 128) {
            float v = p[c];
            m = fmaxf(m, v);
            slin += v;
        }
        m = blockReduceMax<128>(m, sbuf);
        slin = blockReduceSum<128>(slin, sbuf);
        float se = 0.0f;
        for (int c = threadIdx.x; c < NCLS; c += 128) se += __expf(p[c] - m);
        se = blockReduceSum<128>(se, sbuf);
        if (threadIdx.x == 0) {
            float lse = m + __logf(se);
            int t = (int)g_tcls[i];
            float loss = 0.9f * (lse - p[t]) + 0.1f * (lse - slin / (float)NCLS);
            atomicAdd(&g_ce, (double)loss);
        }
    } else {
        const int z = b - NR - BATCH;
        float4* dst = (float4*)(g_rows) + (size_t)z * (NR * 8 / 4 / ZBLK);
        for (int i = threadIdx.x; i < NR * 8 / 4 / ZBLK; i += 128)
            dst[i] = make_float4(0.f, 0.f, 0.f, 0.f);
    }
}

// ---------------- fused symmetric int8 GEMM + masked reductions ----------------
__device__ __forceinline__ void cp_async16(void* smem_dst, const void* gmem_src) {
    unsigned s = (unsigned)__cvta_generic_to_shared(smem_dst);
    asm volatile("cp.async.cg.shared.global [%0], [%1], 16;\n" :: "r"(s), "l"(gmem_src));
}

#define LDSB 80         // int8 row stride bytes: 64 + 16 pad (conflict-free LDSM)
#define LDG 132         // staging row stride (int32 elems)
#define STG_ELEMS (128 * LDSB)           // per-tensor per-stage bytes
#define STAGE_ELEMS (2 * STG_ELEMS)      // A+B per stage (20480 B)
#define ESH_OFF (128 * LDG * 4)          // e-array offset: after stgi (67584 B)
#define GEMM_SMEM (ESH_OFF + 128 * LDG * 2)   // + bf16 e-array (33792) = 101376 B
#define INV_Q2 (1.0f / 16129.0f)         // 1/127^2

__global__ void __launch_bounds__(256, 2) gemm_fused_kernel() {
    extern __shared__ char dsm[];
    signed char* sm = (signed char*)dsm;              // [3][A:128*80 | B:128*80]
    int* stgi = (int*)dsm;                            // 128*LDG int32 (reused)
    __nv_bfloat16* esh = (__nv_bfloat16*)(dsm + ESH_OFF);  // 128*LDG bf16 exp cache
    __shared__ unsigned char gA[32], gB[32];          // per-group (4 rows) class codes

    constexpr int NKIT = DD / 64;                     // 8 K-iterations

    // triangular tile decode: blockIdx.x in [0, 2080)
    int idx = blockIdx.x;
    int r = 0;
    while (idx >= 64 - r) { idx -= 64 - r; r++; }
    const int bm = r * 128;
    const int bn = (r + idx) * 128;

    const int tid = threadIdx.x;
    const int warp = tid >> 5;
    const int wm = (warp & 3) * 32;
    const int wn = (warp >> 2) * 64;

    auto load_stage = [&](int k0, int s) {
        signed char* As = sm + s * STAGE_ELEMS;
        signed char* Bs = As + STG_ELEMS;
#pragma unroll
        for (int it = 0; it < 2; it++) {
            int c = it * 256 + tid;                   // 512 chunks of 16B per tensor
            int row = c >> 2;
            int col = (c & 3) * 16;
            cp_async16(&As[row * LDSB + col], g_q + (size_t)(bm + row) * DD + k0 * 64 + col);
            cp_async16(&Bs[row * LDSB + col], g_q + (size_t)(bn + row) * DD + k0 * 64 + col);
        }
    };

    wmma::fragment<wmma::accumulator, 16, 16, 16, int> acc[2][4];
#pragma unroll
    for (int i = 0; i < 2; i++)
#pragma unroll
        for (int j = 0; j < 4; j++) wmma::fill_fragment(acc[i][j], 0);

    load_stage(0, 0);
    asm volatile("cp.async.commit_group;\n");
    load_stage(1, 1);
    asm volatile("cp.async.commit_group;\n");

    for (int k0 = 0; k0 < NKIT; k0++) {
        if (k0 < NKIT - 1) asm volatile("cp.async.wait_group 1;\n");
        else               asm volatile("cp.async.wait_group 0;\n");
        __syncthreads();                               // all warps done reading stage (k0-1)%3
        if (k0 + 2 < NKIT) {
            load_stage(k0 + 2, (k0 + 2) % 3);          // overwrites stage (k0-1)%3 — safe
            asm volatile("cp.async.commit_group;\n");
        }
        const int s = k0 % 3;
        const signed char* As = sm + s * STAGE_ELEMS;
        const signed char* Bs = As + STG_ELEMS;
#pragma unroll
        for (int kk = 0; kk < 4; kk++) {
            wmma::fragment<wmma::matrix_a, 16, 16, 16, signed char, wmma::row_major> a[2];
            wmma::fragment<wmma::matrix_b, 16, 16, 16, signed char, wmma::col_major> b[4];
#pragma unroll
            for (int i = 0; i < 2; i++)
                wmma::load_matrix_sync(a[i], &As[(wm + i * 16) * LDSB + kk * 16], LDSB);
#pragma unroll
            for (int j = 0; j < 4; j++)
                wmma::load_matrix_sync(b[j], &Bs[(wn + j * 16) * LDSB + kk * 16], LDSB);
#pragma unroll
            for (int i = 0; i < 2; i++)
#pragma unroll
                for (int j = 0; j < 4; j++) wmma::mma_sync(acc[i][j], a[i], b[j], acc[i][j]);
        }
    }
    __syncthreads();                                   // before reusing smem as staging

    // stage int32 tile in smem
#pragma unroll
    for (int i = 0; i < 2; i++)
#pragma unroll
        for (int j = 0; j < 4; j++)
            wmma::store_matrix_sync(stgi + (size_t)(wm + i * 16) * LDG + wn + j * 16,
                                    acc[i][j], LDG, wmma::mem_row_major);
    if (tid < 32) gA[tid] = g_tcls[(bm >> 2) + tid];
    else if (tid < 64) gB[tid - 32] = g_tcls[(bn >> 2) + (tid - 32)];
    __syncthreads();

    const bool offdiag = (bm != bn);

    // ---- row pass: 2 threads per anchor row (bm+a); groups of 4 cols share class ----
    // accumulate T, EP(=sum of pi-col e), EPv, P(=class-match pi-col e), Pv,
    // Ms(=class-match group sums), Mvs; derive Q=EP-P, Qv=EPv-Pv, R=Ms-P, Rv=Mvs-Pv
    {
        const int a = tid >> 1, h = tid & 1;
        const int myc = gA[a >> 2], pi = a & 3;
        float T = 0.f, EP = 0.f, EPv = 0.f, P = 0.f, Pv = 0.f, Ms = 0.f, Mvs = 0.f;
        const int4* rp = (const int4*)(stgi + (size_t)a * LDG + h * 64);
        __nv_bfloat16* ep_row = esh + (size_t)a * LDG + h * 64;
#pragma unroll
        for (int g = 0; g < 16; g++) {
            int4 q4 = rp[g];
            float v0 = (float)q4.x * INV_Q2, v1 = (float)q4.y * INV_Q2;
            float v2 = (float)q4.z * INV_Q2, v3 = (float)q4.w * INV_Q2;
            float e0 = __expf(v0), e1 = __expf(v1), e2 = __expf(v2), e3 = __expf(v3);
            if (offdiag) {                 // cache exps for the col pass (symmetric values)
                __nv_bfloat162 p0 = __floats2bfloat162_rn(e0, e1);
                __nv_bfloat162 p1 = __floats2bfloat162_rn(e2, e3);
                *(uint2*)(ep_row + g * 4) = make_uint2(*(uint32_t*)&p0, *(uint32_t*)&p1);
            }
            float s = (e0 + e1) + (e2 + e3);
            float vs = (v0 + v1) + (v2 + v3);
            float ep = pi == 0 ? e0 : pi == 1 ? e1 : pi == 2 ? e2 : e3;
            float vp = pi == 0 ? v0 : pi == 1 ? v1 : pi == 2 ? v2 : v3;
            float m = (gB[h * 16 + g] == myc) ? 1.0f : 0.0f;
            T += s;
            EP += ep;        EPv += vp;
            P += m * ep;     Pv += m * vp;
            Ms += m * s;     Mvs += m * vs;
        }
        T += __shfl_xor_sync(0xffffffffu, T, 1);
        EP += __shfl_xor_sync(0xffffffffu, EP, 1);
        EPv += __shfl_xor_sync(0xffffffffu, EPv, 1);
        P += __shfl_xor_sync(0xffffffffu, P, 1);
        Pv += __shfl_xor_sync(0xffffffffu, Pv, 1);
        Ms += __shfl_xor_sync(0xffffffffu, Ms, 1);
        Mvs += __shfl_xor_sync(0xffffffffu, Mvs, 1);
        if (h == 0) {
            float* d = g_rows + (size_t)(bm + a) * 8;
            atomicAdd(d + 0, T);       atomicAdd(d + 1, P);
            atomicAdd(d + 2, EP - P);  atomicAdd(d + 3, Ms - P);
            atomicAdd(d + 4, Pv);      atomicAdd(d + 5, EPv - Pv);
            atomicAdd(d + 6, Mvs - Pv);
        }
    }

    // ---- col pass (off-diagonal only): anchors bn+c over rows of bm block ----
    if (offdiag) {
        __syncthreads();                               // esh written by row pass
        const int c = tid >> 1, h = tid & 1;
        const int myc = gB[c >> 2], pi = c & 3;
        float T = 0.f, EP = 0.f, EPv = 0.f, P = 0.f, Pv = 0.f, Ms = 0.f, Mvs = 0.f;
#pragma unroll
        for (int g = 0; g < 16; g++) {
            const int j0 = h * 64 + g * 4;
            float v0 = (float)stgi[(j0 + 0) * LDG + c] * INV_Q2;
            float v1 = (float)stgi[(j0 + 1) * LDG + c] * INV_Q2;
            float v2 = (float)stgi[(j0 + 2) * LDG + c] * INV_Q2;
            float v3 = (float)stgi[(j0 + 3) * LDG + c] * INV_Q2;
            float e0 = __bfloat162float(esh[(j0 + 0) * LDG + c]);
            float e1 = __bfloat162float(esh[(j0 + 1) * LDG + c]);
            float e2 = __bfloat162float(esh[(j0 + 2) * LDG + c]);
            float e3 = __bfloat162float(esh[(j0 + 3) * LDG + c]);
            float s = (e0 + e1) + (e2 + e3);
            float vs = (v0 + v1) + (v2 + v3);
            float ep = pi == 0 ? e0 : pi == 1 ? e1 : pi == 2 ? e2 : e3;
            float vp = pi == 0 ? v0 : pi == 1 ? v1 : pi == 2 ? v2 : v3;
            float m = (gA[h * 16 + g] == myc) ? 1.0f : 0.0f;
            T += s;
            EP += ep;        EPv += vp;
            P += m * ep;     Pv += m * vp;
            Ms += m * s;     Mvs += m * vs;
        }
        T += __shfl_xor_sync(0xffffffffu, T, 1);
        EP += __shfl_xor_sync(0xffffffffu, EP, 1);
        EPv += __shfl_xor_sync(0xffffffffu, EPv, 1);
        P += __shfl_xor_sync(0xffffffffu, P, 1);
        Pv += __shfl_xor_sync(0xffffffffu, Pv, 1);
        Ms += __shfl_xor_sync(0xffffffffu, Ms, 1);
        Mvs += __shfl_xor_sync(0xffffffffu, Mvs, 1);
        if (h == 0) {
            float* d = g_rows + (size_t)(bn + c) * 8;
            atomicAdd(d + 0, T);       atomicAdd(d + 1, P);
            atomicAdd(d + 2, EP - P);  atomicAdd(d + 3, Ms - P);
            atomicAdd(d + 4, Pv);      atomicAdd(d + 5, EPv - Pv);
            atomicAdd(d + 6, Mvs - Pv);
        }
    }
}

// ---------------- assemble (32 blocks) + last-block finalize ----------------
// E1 = T-P; E2 = T-P-Q-R.  x = e^{-v}E >= ~700:
// sum_pos log1p(e^{-v}E) = n*logE - sum(v) + sum(e^v)/E
__global__ void assemble_kernel(float* out) {
    const int i = blockIdx.x * 256 + threadIdx.x;      // 8192 threads over 32 blocks
    const float* b = g_rows + (size_t)i * 8;
    float T = b[0], P = b[1], Q = b[2], R = b[3], Pv = b[4], Qv = b[5], Rv = b[6];
    float E1 = T - P;
    float E2 = E1 - Q - R;
    float ct = (float)g_chist[g_tcls[i >> 2]];
    float c = ct * __logf(E1) - Pv + P / E1
            + (2048.0f + 2.0f * ct) * __logf(E2) - (Qv + Rv) + (Q + R) / E2;
    double d = (double)c;
#pragma unroll
    for (int o = 16; o > 0; o >>= 1) d += __shfl_xor_sync(0xffffffffu, d, o);
    if ((threadIdx.x & 31) == 0) atomicAdd(&g_np, d);
    __syncthreads();
    if (threadIdx.x == 0) {
        __threadfence();
        unsigned done = atomicAdd(&g_done, 1u);
        if (done == 31u) {                             // last block finalizes
            __threadfence();
            double np = atomicAdd(&g_np, 0.0);         // ordered read
            double ce = g_ce;
            out[0] = (float)(ce / (double)BATCH + 0.5 * (np / (double)NR));
            g_done = 0u;                               // reset for next replay
        }
    }
}

// ---------------- launch ----------------
extern "C" void kernel_launch(void* const* d_in, const int* in_sizes, int n_in,
                              void* d_out, int out_size) {
    const float* pred = nullptr;
    const float* x_part = nullptr;
    const unsigned int* traw = nullptr;
    for (int i = 0; i < n_in; i++) {
        if (in_sizes[i] == BATCH * NCLS)      pred   = (const float*)d_in[i];
        else if (in_sizes[i] == NR * DD)      x_part = (const float*)d_in[i];
        else if (in_sizes[i] == BATCH)        traw   = (const unsigned int*)d_in[i];
    }
    float* out = (float*)d_out;

    cudaFuncSetAttribute(gemm_fused_kernel, cudaFuncAttributeMaxDynamicSharedMemorySize,
                         GEMM_SMEM);

    decode_targets_kernel<<<1, 1024>>>(traw);
    norm_ce_kernel<<<NR + BATCH + ZBLK, 128>>>(x_part, pred);
    gemm_fused_kernel<<<2080, 256, GEMM_SMEM>>>();
    assemble_kernel<<<32, 256>>>(out);
}